// round 14
// baseline (speedup 1.0000x reference)
#include <cuda_runtime.h>
#include <cuda_bf16.h>
#include <cstdint>

// YOLOv3 decode: x [16, 255, 76, 76] fp32 -> out [16, 3*5776, 85] fp32
// R14 = R13 architecture (input on the bulk-async engine, double-buffered,
// mbarrier complete_tx; warps only LDS->activate->STS; TMA bulk store out)
// WITHOUT the 2D tensor map that faulted: per tile, warp 0 issues 85x 1D
// cp.async.bulk (one 256B channel row each). All alignments manifest.
// Tail chunk remapped to hw0=5712 (identical recompute, benign double write).

#define YHW    5776
#define YC     85
#define HWT    64
#define YTPB   256
#define CHUNKS 91
#define NTILES (48 * CHUNKS)          // 4368
#define NBLK   444                    // 148 SMs x 3 CTAs
#define TILE_BYTES (HWT * YC * 4)     // 21760
#define ROW_BYTES  (HWT * 4)          // 256

// dynamic smem layout (bytes)
#define SM_MBAR 0                     // 2 x 8B mbarriers
#define SM_IN   32
#define SM_OUT  (SM_IN + 2 * TILE_BYTES)
#define SM_TOTAL (SM_OUT + TILE_BYTES)   // 65312

__device__ __forceinline__ float ytanh(float x) {
    float r;
    asm("tanh.approx.f32 %0, %1;" : "=f"(r) : "f"(x));
    return r;
}
__device__ __forceinline__ float ysig(float v) {
    return fmaf(0.5f, ytanh(0.5f * v), 0.5f);
}

__device__ __forceinline__ void mbar_wait(uint32_t mbar, uint32_t ph) {
    asm volatile(
        "{\n\t.reg .pred P;\n\t"
        "WL%=:\n\t"
        "mbarrier.try_wait.parity.acquire.cta.shared::cta.b64 P, [%0], %1, 0x989680;\n\t"
        "@!P bra WL%=;\n\t}"
        :: "r"(mbar), "r"(ph) : "memory");
}

__device__ __forceinline__ int tile_hw0(int chunk) {
    return (chunk == CHUNKS - 1) ? (YHW - HWT) : chunk * HWT;   // tail remap
}

// Warp 0 collective: expect_tx(TILE_BYTES) then 85 x 1D bulk row copies.
__device__ __forceinline__ void tma_load_tile(
    const float* __restrict__ x, int s, int hw0,
    uint32_t dst, uint32_t mbar, int lane)
{
    if (lane == 0)
        asm volatile("mbarrier.arrive.expect_tx.shared.b64 _, [%0], %1;"
                     :: "r"(mbar), "r"((uint32_t)TILE_BYTES) : "memory");
    __syncwarp();
    const float* base = x + (size_t)s * YC * YHW + hw0;
    #pragma unroll
    for (int r = 0; r < 3; r++) {
        const int c = lane + r * 32;               // 0..84 (96>85: guard)
        if (c < YC) {
            const float* src = base + (size_t)c * YHW;
            asm volatile(
                "cp.async.bulk.shared::cta.global.mbarrier::complete_tx::bytes "
                "[%0], [%1], %2, [%3];"
                :: "r"(dst + c * ROW_BYTES), "l"(src),
                   "r"((uint32_t)ROW_BYTES), "r"(mbar) : "memory");
        }
    }
}

__global__ __launch_bounds__(YTPB) void Yolo_59966333387037_kernel(
    const float* __restrict__ x,
    const float* __restrict__ anchors,
    float* __restrict__ out)
{
    extern __shared__ __align__(16) char smem[];
    const uint32_t sb  = (uint32_t)__cvta_generic_to_shared(smem);
    const uint32_t mb0 = sb + SM_MBAR;
    float* outb        = (float*)(smem + SM_OUT);

    const int tid  = threadIdx.x;
    const int wid  = tid >> 5;
    const int lane = tid & 31;
    const int hwe  = 2 * lane;                    // even hw within tile

    if (tid == 0) {
        asm volatile("mbarrier.init.shared.b64 [%0], 1;" :: "r"(mb0) : "memory");
        asm volatile("mbarrier.init.shared.b64 [%0], 1;" :: "r"(mb0 + 8) : "memory");
    }
    __syncthreads();

    // Prologue: fill both pipeline stages (warp 0).
    if (wid == 0) {
        #pragma unroll
        for (int j = 0; j < 2; j++) {
            const int tile = blockIdx.x + j * NBLK;    // < NTILES (NBLK*2 < NTILES)
            const int s    = tile / CHUNKS;
            const int c    = tile - s * CHUNKS;
            tma_load_tile(x, s, tile_hw0(c),
                          sb + SM_IN + j * TILE_BYTES, mb0 + 8 * j, lane);
        }
    }

    int it = 0;
    for (int tile = blockIdx.x; tile < NTILES; tile += NBLK, ++it) {
        const int s     = tile / CHUNKS;
        const int chunk = tile - s * CHUNKS;
        const int a     = s % 3;
        const float aw  = __ldg(anchors + 2 * a)     * (1.0f / 608.0f);
        const float ah  = __ldg(anchors + 2 * a + 1) * (1.0f / 608.0f);
        const int hw0   = tile_hw0(chunk);
        const int k     = it & 1;
        const int ph    = (it >> 1) & 1;

        // Out buffer free (previous bulk store drained smem reads) + input here.
        if (tid == 0)
            asm volatile("cp.async.bulk.wait_group.read 0;" ::: "memory");
        mbar_wait(mb0 + 8 * k, ph);
        __syncthreads();

        const float* inb = (const float*)(smem + SM_IN + k * TILE_BYTES);

        // 22 warp-units: g=0..20 channel quads, g=21 -> c==84. 64 hw each.
        #pragma unroll 3
        for (int g = wid; g < 22; g += 8) {
            if (g < 21) {
                const int c0 = g * 4;
                const float2* p = (const float2*)inb + c0 * (HWT / 2) + lane;
                float2 va = p[0];                   // channel c0
                float2 vb = p[HWT / 2];             // c0+1
                float2 vc = p[HWT];                 // c0+2
                float2 vd = p[3 * (HWT / 2)];       // c0+3
                if (g == 0) {
                    const unsigned hw = (unsigned)(hw0 + hwe);     // even
                    const unsigned hh = (hw * 55189u) >> 22;       // hw / 76
                    const unsigned ww = hw - hh * 76u;             // even
                    const float fw = (float)ww, fh = (float)hh;
                    va.x = (ysig(va.x) + fw)        * (1.0f / 76.0f);
                    va.y = (ysig(va.y) + fw + 1.0f) * (1.0f / 76.0f);
                    vb.x = (ysig(vb.x) + fh)        * (1.0f / 76.0f);
                    vb.y = (ysig(vb.y) + fh)        * (1.0f / 76.0f);
                    vc.x = __expf(vc.x) * aw;  vc.y = __expf(vc.y) * aw;
                    vd.x = __expf(vd.x) * ah;  vd.y = __expf(vd.y) * ah;
                } else {
                    va.x = ysig(va.x); va.y = ysig(va.y);
                    vb.x = ysig(vb.x); vb.y = ysig(vb.y);
                    vc.x = ysig(vc.x); vc.y = ysig(vc.y);
                    vd.x = ysig(vd.x); vd.y = ysig(vd.y);
                }
                float* d = outb + (size_t)hwe * YC + c0;
                *(float2*)(d)     = make_float2(va.x, vb.x);   // even row STS.64
                *(float2*)(d + 2) = make_float2(vc.x, vd.x);
                d[YC]     = va.y;                              // odd row scalar
                d[YC + 1] = vb.y;
                d[YC + 2] = vc.y;
                d[YC + 3] = vd.y;
            } else {
                const float2* p = (const float2*)inb + 84 * (HWT / 2) + lane;
                float2 v = p[0];
                float* d = outb + (size_t)hwe * YC + 84;
                d[0]  = ysig(v.x);
                d[YC] = ysig(v.y);
            }
        }
        __syncthreads();

        // Store out tile (thread 0) + refill this in-stage (warp 0).
        if (tid == 0) {
            asm volatile("fence.proxy.async.shared::cta;" ::: "memory");
            float* dst = out + ((size_t)s * YHW + hw0) * YC;
            asm volatile(
                "cp.async.bulk.global.shared::cta.bulk_group [%0], [%1], %2;"
                :: "l"(dst), "r"(sb + SM_OUT), "r"((uint32_t)TILE_BYTES) : "memory");
            asm volatile("cp.async.bulk.commit_group;" ::: "memory");
        }
        if (wid == 0) {
            const int tn = tile + 2 * NBLK;
            if (tn < NTILES) {
                const int sn = tn / CHUNKS;
                const int cn = tn - sn * CHUNKS;
                tma_load_tile(x, sn, tile_hw0(cn),
                              sb + SM_IN + k * TILE_BYTES, mb0 + 8 * k, lane);
            }
        }
    }

    if (tid == 0)
        asm volatile("cp.async.bulk.wait_group 0;" ::: "memory");
}

extern "C" void kernel_launch(void* const* d_in, const int* in_sizes, int n_in,
                              void* d_out, int out_size)
{
    const float* x       = (const float*)d_in[0];
    const float* anchors = (const float*)d_in[1];
    float* out           = (float*)d_out;

    cudaFuncSetAttribute(Yolo_59966333387037_kernel,
                         cudaFuncAttributeMaxDynamicSharedMemorySize, SM_TOTAL);
    Yolo_59966333387037_kernel<<<NBLK, YTPB, SM_TOTAL>>>(x, anchors, out);
}

// round 16
// speedup vs baseline: 1.0981x; 1.0981x over previous
#include <cuda_runtime.h>
#include <cuda_bf16.h>
#include <cstdint>

// YOLOv3 decode: x [16, 255, 76, 76] fp32 -> out [16, 3*5776, 85] fp32
// R15: warp-autonomous tiles — NO CTA-wide synchronization anywhere.
// Each warp owns tiles of 8 hw x 85 c (2720B):
//   22x LDG.32 (4 fully-used 32B sectors each, hw-aligned), activations,
//   STS into a per-warp slab in final [hw][c] layout (contiguous output
//   region), then lane 0 bulk-stores 2720B and only waits .read-drain at the
//   next tile. 5776/8 = 722 exact -> no tail anywhere.
// Rationale: R10-R12 plateau at ~27us kernel / DRAM 63% with nothing
// saturated; the shared feature is phase-aligned CTA barriers making the
// DRAM request stream bursty. Free-running warps desynchronize it.

#define YHW   5776
#define YC    85
#define TPW   8                      // hw per warp-tile
#define YTPB  256
#define WPB   8
#define TPS   (YHW / TPW)            // 722 tiles per slice
#define NTILES (48 * TPS)            // 34656
#define NBLK  888                    // 148 SMs x 6 CTAs
#define NWARPS (NBLK * WPB)          // 7104
#define SLAB_BYTES (TPW * YC * 4)    // 2720

__device__ __forceinline__ float ytanh(float x) {
    float r;
    asm("tanh.approx.f32 %0, %1;" : "=f"(r) : "f"(x));
    return r;
}
__device__ __forceinline__ float ysig(float v) {
    return fmaf(0.5f, ytanh(0.5f * v), 0.5f);     // 1 MUFU + 1 FMA
}

__global__ __launch_bounds__(YTPB, 6) void Yolo_59966333387037_kernel(
    const float* __restrict__ x,
    const float* __restrict__ anchors,
    float* __restrict__ out)
{
    __shared__ __align__(16) float sm[WPB][TPW * YC];   // 8 x 2720 B

    const int wid  = threadIdx.x >> 5;
    const int lane = threadIdx.x & 31;
    const int cg   = lane >> 3;        // channel sub-index 0..3
    const int hwl  = lane & 7;         // hw within tile

    float* slab = sm[wid];
    const uint32_t slab_s = (uint32_t)__cvta_generic_to_shared(slab);

    const int gw = blockIdx.x * WPB + wid;       // global warp id

    for (int tile = gw; tile < NTILES; tile += NWARPS) {
        const int s   = tile / TPS;              // slice 0..47
        const int t   = tile - s * TPS;
        const int hw0 = t * TPW;
        const int a   = s - (s / 3) * 3;

        const float* __restrict__ base = x + (size_t)s * YC * YHW + hw0;

        // Previous bulk store must have finished READING this slab.
        if (lane == 0)
            asm volatile("cp.async.bulk.wait_group.read 0;" ::: "memory");
        __syncwarp();

        // Request 0: channels 0..3 (special activations), 8 hw per channel.
        {
            const float v = base[(size_t)cg * YHW + hwl];
            float r;
            if (cg == 0) {
                const unsigned hw = (unsigned)(hw0 + hwl);
                const unsigned hh = (hw * 55189u) >> 22;     // hw / 76
                const unsigned ww = hw - hh * 76u;
                r = (ysig(v) + (float)ww) * (1.0f / 76.0f);
            } else if (cg == 1) {
                const unsigned hw = (unsigned)(hw0 + hwl);
                const unsigned hh = (hw * 55189u) >> 22;
                r = (ysig(v) + (float)hh) * (1.0f / 76.0f);
            } else if (cg == 2) {
                r = __expf(v) * (__ldg(anchors + 2 * a) * (1.0f / 608.0f));
            } else {
                r = __expf(v) * (__ldg(anchors + 2 * a + 1) * (1.0f / 608.0f));
            }
            slab[hwl * YC + cg] = r;
        }

        // Requests 1..20: channels 4..83, pure sigmoid. Loads batch for MLP.
        float v[20];
        #pragma unroll
        for (int r = 0; r < 20; r++)
            v[r] = base[(size_t)(4 * (r + 1) + cg) * YHW + hwl];
        #pragma unroll
        for (int r = 0; r < 20; r++)
            slab[hwl * YC + 4 * (r + 1) + cg] = ysig(v[r]);

        // Channel 84: lanes 0..7 only.
        if (lane < 8) {
            const float u = base[(size_t)84 * YHW + hwl];
            slab[hwl * YC + 84] = ysig(u);
        }
        __syncwarp();

        if (lane == 0) {
            asm volatile("fence.proxy.async.shared::cta;" ::: "memory");
            float* dst = out + ((size_t)s * YHW + hw0) * YC;   // 16B-aligned
            asm volatile(
                "cp.async.bulk.global.shared::cta.bulk_group [%0], [%1], %2;"
                :: "l"(dst), "r"(slab_s), "r"((uint32_t)SLAB_BYTES) : "memory");
            asm volatile("cp.async.bulk.commit_group;" ::: "memory");
        }
    }

    // Drain before exit.
    if (lane == 0)
        asm volatile("cp.async.bulk.wait_group 0;" ::: "memory");
}

extern "C" void kernel_launch(void* const* d_in, const int* in_sizes, int n_in,
                              void* d_out, int out_size)
{
    const float* x       = (const float*)d_in[0];
    const float* anchors = (const float*)d_in[1];
    float* out           = (float*)d_out;

    Yolo_59966333387037_kernel<<<NBLK, YTPB>>>(x, anchors, out);
}

// round 17
// speedup vs baseline: 1.1208x; 1.0207x over previous
#include <cuda_runtime.h>
#include <cuda_bf16.h>
#include <cstdint>

// YOLOv3 decode: x [16, 255, 76, 76] fp32 -> out [16, 3*5776, 85] fp32
// R17 = R10 with LDG.128 loads. Warp-unit = (channel PAIR, 64 hw):
// lanes 0-15 -> channel c0 (float4 = hw 4l..4l+3), lanes 16-31 -> c0+1.
// 43 load instructions/tile (vs 88), 512B in flight per instruction (vs 256).
// Special channels align to pairs: unit0 = (c0,c1) sigmoid+grid, unit1 =
// (c2,c3) exp*anchor, units 2..41 sigmoid, unit42 = c84 low half-warp.
// Rest identical to R10: single 21.76KB smem tile in output layout,
// 8 CTAs/SM, persistent grid, TMA bulk store, wait_group.read 0.

#define YHW    5776
#define YC     85
#define HWT    64
#define YTPB   256
#define CHUNKS 91                  // 90 full + tail of 16 hw
#define NTILES (48 * CHUNKS)       // 4368
#define NBLK   1184                // 148 x 8

__device__ __forceinline__ float ytanh(float x) {
    float r;
    asm("tanh.approx.f32 %0, %1;" : "=f"(r) : "f"(x));
    return r;
}
__device__ __forceinline__ float ysig(float v) {
    return fmaf(0.5f, ytanh(0.5f * v), 0.5f);     // 1 MUFU + 1 FMA
}

template <bool TAIL>
__device__ __forceinline__ void load_tile(
    const float* __restrict__ xs, float* __restrict__ smb,
    int hw0, int nhw, float aw, float ah, int wid, int lane)
{
    const int hl  = lane & 15;            // position within half-warp
    const int hi  = lane >> 4;            // 0: channel c0, 1: c0+1
    const int hwl = 4 * hl;               // first hw of this lane's float4

    // 43 warp-units: u=0..41 channel pairs (c0 = 2u + hi), u=42 -> c84.
    #pragma unroll 3
    for (int u = wid; u < 43; u += 8) {
        if (TAIL && hwl >= nhw) continue;
        if (u < 42) {
            const int c = 2 * u + hi;
            const float4 v = *(const float4*)(xs + (size_t)c * YHW + hwl);
            float r[4] = {v.x, v.y, v.z, v.w};
            if (u == 0) {
                // c==0: (sig+w)/76 ; c==1: (sig+h)/76
                #pragma unroll
                for (int j = 0; j < 4; j++) {
                    const unsigned hw = (unsigned)(hw0 + hwl + j);
                    const unsigned hh = (hw * 55189u) >> 22;      // hw / 76
                    const unsigned ww = hw - hh * 76u;
                    const float g = hi ? (float)hh : (float)ww;
                    r[j] = (ysig(r[j]) + g) * (1.0f / 76.0f);
                }
            } else if (u == 1) {
                // c==2: exp*aw ; c==3: exp*ah
                const float sc = hi ? ah : aw;
                #pragma unroll
                for (int j = 0; j < 4; j++) r[j] = __expf(r[j]) * sc;
            } else {
                #pragma unroll
                for (int j = 0; j < 4; j++) r[j] = ysig(r[j]);
            }
            float* d = smb + (size_t)hwl * YC + c;
            #pragma unroll
            for (int j = 0; j < 4; j++) d[j * YC] = r[j];   // ~2-way conflicts
        } else if (hi == 0) {
            // c == 84, low half-warp only
            const float4 v = *(const float4*)(xs + (size_t)84 * YHW + hwl);
            float* d = smb + (size_t)hwl * YC + 84;
            d[0]      = ysig(v.x);
            d[YC]     = ysig(v.y);
            d[2 * YC] = ysig(v.z);
            d[3 * YC] = ysig(v.w);
        }
    }
}

__global__ __launch_bounds__(YTPB, 8) void Yolo_59966333387037_kernel(
    const float* __restrict__ x,
    const float* __restrict__ anchors,
    float* __restrict__ out)
{
    __shared__ __align__(16) float sm[HWT * YC];   // 21760 B, output layout

    const int wid  = threadIdx.x >> 5;
    const int lane = threadIdx.x & 31;

    for (int tile = blockIdx.x; tile < NTILES; tile += NBLK) {
        const int s     = tile / CHUNKS;
        const int chunk = tile - s * CHUNKS;
        const int a     = s % 3;
        const float aw  = __ldg(anchors + 2 * a)     * (1.0f / 608.0f);
        const float ah  = __ldg(anchors + 2 * a + 1) * (1.0f / 608.0f);
        const int hw0   = chunk * HWT;
        const int nhw   = min(HWT, YHW - hw0);      // 64 or 16
        const float* xs = x + (size_t)s * YC * YHW + hw0;

        // Previous TMA store must have finished READING smem before overwrite.
        if (threadIdx.x == 0)
            asm volatile("cp.async.bulk.wait_group.read 0;" ::: "memory");
        __syncthreads();

        if (nhw == HWT) load_tile<false>(xs, sm, hw0, nhw, aw, ah, wid, lane);
        else            load_tile<true >(xs, sm, hw0, nhw, aw, ah, wid, lane);
        __syncthreads();

        if (threadIdx.x == 0) {
            asm volatile("fence.proxy.async.shared::cta;" ::: "memory");
            uint32_t saddr;
            asm("{ .reg .u64 t; cvta.to.shared.u64 t, %1; cvt.u32.u64 %0, t; }"
                : "=r"(saddr) : "l"((const void*)sm));
            float* dst = out + ((size_t)s * YHW + hw0) * YC;
            const int bytes = nhw * YC * 4;         // 21760 or 5440
            asm volatile(
                "cp.async.bulk.global.shared::cta.bulk_group [%0], [%1], %2;"
                :: "l"(dst), "r"(saddr), "r"(bytes) : "memory");
            asm volatile("cp.async.bulk.commit_group;" ::: "memory");
        }
    }

    if (threadIdx.x == 0)
        asm volatile("cp.async.bulk.wait_group 0;" ::: "memory");
}

extern "C" void kernel_launch(void* const* d_in, const int* in_sizes, int n_in,
                              void* d_out, int out_size)
{
    const float* x       = (const float*)d_in[0];
    const float* anchors = (const float*)d_in[1];
    float* out           = (float*)d_out;

    Yolo_59966333387037_kernel<<<NBLK, YTPB>>>(x, anchors, out);
}